// round 11
// baseline (speedup 1.0000x reference)
#include <cuda_runtime.h>
#include <cuda_bf16.h>
#include <math.h>
#include <cstdio>
#include <cstdint>

// ---------------------------------------------------------------------------
// SlotAttentionEncoder: B=32, Cin=5, HID=64, H=W=128, K=7, Q=64, 3 iters
// Round 9: convs use packed fma.rn.f32x2 (dual-fp32 FMA, 2x FFMA throughput,
// bit-identical math) pairing over output channels; attn NBLK 16->64.
// tcgen05 is unusable: harness compiles to plain sm_103 (no 'a' features).
// ---------------------------------------------------------------------------

#define Bn   32
#define HID  64
#define Npix 16384
#define Ks   7
#define Qd   64
#define NBLK 64

__device__ float g_buf1[(size_t)Bn * HID * Npix];
__device__ float g_buf2[(size_t)Bn * HID * Npix];
__device__ float g_keys[(size_t)Bn * Npix * Qd];
__device__ float g_vals[(size_t)Bn * Npix * Qd];
__device__ float g_valsum[Bn * Qd];
__device__ float g_q[Bn * Ks * Qd];
__device__ float g_Ppart[(size_t)Bn * NBLK * Ks * Qd];
__device__ float g_attsum[Bn * NBLK * Ks];

typedef unsigned long long ull;
__device__ __forceinline__ ull ffma2(ull a, ull b, ull c) {
    ull d;
    asm("fma.rn.f32x2 %0, %1, %2, %3;" : "=l"(d) : "l"(a), "l"(b), "l"(c));
    return d;
}
__device__ __forceinline__ float lo32(ull v) { return __uint_as_float((unsigned)v); }
__device__ __forceinline__ float hi32(ull v) { return __uint_as_float((unsigned)(v >> 32)); }

// ---------------------------------------------------------------------------
// 5x5 conv, pad 2, NCHW, 64 co. Block: 256 thr -> tile 64co x 8y x 32x.
// Thread: 4 co-pairs x 8 px, FFMA2. Input staged as (v,v) dup float2 so the
// sliding window needs no repacking; weight pairs are naturally adjacent.
// DIR: 0 = ext->buf1, 1 = buf1->buf2, 2 = buf2->buf1
// ---------------------------------------------------------------------------
template <int CI, int CI_CHUNK, bool RELU, int DIR>
__global__ __launch_bounds__(256)
void conv5x5(const float* __restrict__ ext_in, const float* __restrict__ wt,
             const float* __restrict__ bias)
{
    extern __shared__ char smraw[];
    float2* in2 = (float2*)smraw;                                   // dup pairs
    float*  w_s = (float*)(smraw + sizeof(float2) * CI_CHUNK * 12 * 36);

    const float* in  = (DIR == 0) ? ext_in : (DIR == 1 ? g_buf1 : g_buf2);
    float*       out = (DIR == 1) ? g_buf2 : g_buf1;

    const int tid = threadIdx.x;
    const int xg  = tid & 3;          // x group of 8
    const int yy  = (tid >> 2) & 7;   // row in tile
    const int cog = tid >> 5;         // co group of 8 (warp-uniform)
    const int x0  = blockIdx.x * 32;
    const int b   = blockIdx.y >> 4;
    const int y0  = (blockIdx.y & 15) * 8;

    ull acc[4][8];
#pragma unroll
    for (int cc = 0; cc < 4; cc++)
#pragma unroll
        for (int p = 0; p < 8; p++) acc[cc][p] = 0ull;

    for (int ci0 = 0; ci0 < CI; ci0 += CI_CHUNK) {
        __syncthreads();
        for (int e = tid; e < CI_CHUNK * 12 * 36; e += 256) {
            int ci = e / (12 * 36);
            int r  = e - ci * (12 * 36);
            int iy = r / 36, ix = r - iy * 36;
            int gy = y0 + iy - 2, gx = x0 + ix - 2;
            float v = 0.f;
            if ((unsigned)gy < 128u && (unsigned)gx < 128u)
                v = in[((size_t)(b * CI + ci0 + ci) << 14) + (gy << 7) + gx];
            in2[e] = make_float2(v, v);
        }
        for (int e = tid; e < CI_CHUNK * 25 * 64; e += 256) {
            int co  = e & 63;
            int tap = (e >> 6) % 25;
            int ci  = e / (25 * 64);
            w_s[e] = wt[(size_t)co * (CI * 25) + (ci0 + ci) * 25 + tap];
        }
        __syncthreads();

#pragma unroll 1
        for (int ci = 0; ci < CI_CHUNK; ci++) {
#pragma unroll
            for (int ky = 0; ky < 5; ky++) {
                const ull* rowp = (const ull*)&in2[(ci * 12 + yy + ky) * 36 + xg * 8];
                ull xin[12];
#pragma unroll
                for (int j = 0; j < 12; j++) xin[j] = rowp[j];
#pragma unroll
                for (int kx = 0; kx < 5; kx++) {
                    const ull* wp = (const ull*)&w_s[(ci * 25 + ky * 5 + kx) * 64 + cog * 8];
                    ull wq[4];
#pragma unroll
                    for (int cc = 0; cc < 4; cc++) wq[cc] = wp[cc];
#pragma unroll
                    for (int cc = 0; cc < 4; cc++)
#pragma unroll
                        for (int p = 0; p < 8; p++)
                            acc[cc][p] = ffma2(wq[cc], xin[kx + p], acc[cc][p]);
                }
            }
        }
    }

    const int oy = y0 + yy, ox = x0 + xg * 8;
#pragma unroll
    for (int cc = 0; cc < 4; cc++) {
        const int co = cog * 8 + cc * 2;
        const float bl = bias[co], bh = bias[co + 1];
        float rl[8], rh[8];
#pragma unroll
        for (int p = 0; p < 8; p++) {
            float vl = lo32(acc[cc][p]) + bl;
            float vh = hi32(acc[cc][p]) + bh;
            if (RELU) { vl = fmaxf(vl, 0.f); vh = fmaxf(vh, 0.f); }
            rl[p] = vl; rh[p] = vh;
        }
        float* opl = &out[((size_t)(b * HID + co) << 14) + (oy << 7) + ox];
        float* oph = &out[((size_t)(b * HID + co + 1) << 14) + (oy << 7) + ox];
        *(float4*)opl       = make_float4(rl[0], rl[1], rl[2], rl[3]);
        *(float4*)(opl + 4) = make_float4(rl[4], rl[5], rl[6], rl[7]);
        *(float4*)oph       = make_float4(rh[0], rh[1], rh[2], rh[3]);
        *(float4*)(oph + 4) = make_float4(rh[4], rh[5], rh[6], rh[7]);
    }
}

// ---------------------------------------------------------------------------
// LayerNorm over 64 channels + NCHW -> [b][n][c] transpose. buf1 -> buf2.
// ---------------------------------------------------------------------------
__global__ __launch_bounds__(256)
void ln_transpose(const float* __restrict__ g, const float* __restrict__ bta)
{
    __shared__ float t[HID * 33];
    __shared__ float mean_s[32], rstd_s[32];
    const int tid = threadIdx.x;
    const int b = blockIdx.x >> 9, n0 = (blockIdx.x & 511) * 32;
    for (int e = tid; e < HID * 32; e += 256) {
        int c = e >> 5, j = e & 31;
        t[c * 33 + j] = g_buf1[((size_t)(b * HID + c) << 14) + n0 + j];
    }
    __syncthreads();
    if (tid < 32) {
        float s = 0.f, s2 = 0.f;
        for (int c = 0; c < HID; c++) { float v = t[c * 33 + tid]; s += v; s2 += v * v; }
        float m = s * (1.f / HID);
        mean_s[tid] = m;
        rstd_s[tid] = rsqrtf(s2 * (1.f / HID) - m * m + 1e-5f);
    }
    __syncthreads();
    for (int e = tid; e < HID * 32; e += 256) {
        int j = e >> 6, c = e & (HID - 1);
        float v = (t[c * 33 + j] - mean_s[j]) * rstd_s[j] * g[c] + bta[c];
        g_buf2[((size_t)(b * Npix + n0 + j) << 6) + c] = v;
    }
}

// ---------------------------------------------------------------------------
// keys/vals = ed @ {toK,toV}^T + bias. ed = buf2 [b][n][64].
// ---------------------------------------------------------------------------
__global__ __launch_bounds__(256)
void kv_gemm(const float* __restrict__ wk, const float* __restrict__ bk,
             const float* __restrict__ wv, const float* __restrict__ bv)
{
    __shared__ float a_s[32 * 37];
    __shared__ float w_s[32 * 128];
    const int tid = threadIdx.x;
    const int b = blockIdx.y, n0 = blockIdx.x * 32;
    const int og = tid & 31, ng = tid >> 5;
    float acc[4][4];
#pragma unroll
    for (int i = 0; i < 4; i++)
#pragma unroll
        for (int j = 0; j < 4; j++) acc[i][j] = 0.f;
    for (int kc = 0; kc < HID; kc += 32) {
        __syncthreads();
        for (int e = tid; e < 1024; e += 256) {
            int n = e >> 5, k = e & 31;
            a_s[n * 37 + k] = g_buf2[((size_t)(b * Npix + n0 + n) << 6) + kc + k];
        }
        for (int e = tid; e < 4096; e += 256) {
            int k = e >> 7, o = e & 127;
            w_s[e] = (o < 64) ? wk[o * HID + kc + k] : wv[(o - 64) * HID + kc + k];
        }
        __syncthreads();
#pragma unroll 8
        for (int k = 0; k < 32; k++) {
            float av[4];
#pragma unroll
            for (int i = 0; i < 4; i++) av[i] = a_s[(ng * 4 + i) * 37 + k];
            float4 w4 = *(const float4*)&w_s[k * 128 + og * 4];
            float bw[4] = {w4.x, w4.y, w4.z, w4.w};
#pragma unroll
            for (int i = 0; i < 4; i++)
#pragma unroll
                for (int j = 0; j < 4; j++)
                    acc[i][j] = fmaf(av[i], bw[j], acc[i][j]);
        }
    }
#pragma unroll
    for (int i = 0; i < 4; i++) {
        int n = n0 + ng * 4 + i;
#pragma unroll
        for (int j = 0; j < 4; j++) {
            int o = og * 4 + j;
            if (o < 64) g_keys[((size_t)(b * Npix + n) << 6) + o] = acc[i][j] + bk[o];
            else        g_vals[((size_t)(b * Npix + n) << 6) + (o - 64)] = acc[i][j] + bv[o - 64];
        }
    }
}

__global__ __launch_bounds__(256)
void valsum_k()
{
    __shared__ float p_s[4][64];
    const int tid = threadIdx.x, b = blockIdx.x;
    const int q = tid & 63, part = tid >> 6;
    float s = 0.f;
    for (int n = part; n < Npix; n += 4)
        s += g_vals[((size_t)(b * Npix + n) << 6) + q];
    p_s[part][q] = s;
    __syncthreads();
    if (tid < 64)
        g_valsum[b * 64 + tid] = p_s[0][tid] + p_s[1][tid] + p_s[2][tid] + p_s[3][tid];
}

__global__ void copy_q(const float* __restrict__ src, int n)
{
    int i = blockIdx.x * 256 + threadIdx.x;
    if (i < n) g_q[i] = src[i];
}

// ---------------------------------------------------------------------------
// Attention partials. NBLK=64 blocks/batch (256 n each) for occupancy.
// ---------------------------------------------------------------------------
__global__ __launch_bounds__(64)
void attn_k(const float* __restrict__ qg, const float* __restrict__ qb)
{
    __shared__ float kt[64 * 65];
    __shared__ float vt[64 * 65];
    __shared__ float qn_s[Ks][64];
    __shared__ float att_s[Ks][65];
    __shared__ float mr[Ks][2];
    const int tid = threadIdx.x;
    const int b = blockIdx.y, blk = blockIdx.x;
    for (int s = 0; s < Ks; s++) qn_s[s][tid] = g_q[(b * Ks + s) * 64 + tid];
    __syncthreads();
    if (tid < Ks) {
        float sm = 0.f, s2 = 0.f;
        for (int k = 0; k < 64; k++) { float v = qn_s[tid][k]; sm += v; s2 += v * v; }
        float m = sm * (1.f / 64.f);
        mr[tid][0] = m;
        mr[tid][1] = rsqrtf(s2 * (1.f / 64.f) - m * m + 1e-5f);
    }
    __syncthreads();
    for (int s = 0; s < Ks; s++)
        qn_s[s][tid] = (qn_s[s][tid] - mr[s][0]) * mr[s][1] * qg[tid] + qb[tid];
    float pacc[Ks];
#pragma unroll
    for (int s = 0; s < Ks; s++) pacc[s] = 0.f;
    float asum_acc = 0.f;
    const int nbase = blk * (Npix / NBLK);
    for (int t = 0; t < (Npix / NBLK) / 64; t++) {
        int n0 = nbase + t * 64;
        __syncthreads();
        for (int e = tid; e < 4096; e += 64) {
            int n = e >> 6, qq = e & 63;
            kt[n * 65 + qq] = g_keys[((size_t)(b * Npix + n0 + n) << 6) + qq];
            vt[n * 65 + qq] = g_vals[((size_t)(b * Npix + n0 + n) << 6) + qq];
        }
        __syncthreads();
        float lg[Ks];
#pragma unroll
        for (int s = 0; s < Ks; s++) {
            float d = 0.f;
            for (int k = 0; k < 64; k++) d = fmaf(qn_s[s][k], kt[tid * 65 + k], d);
            lg[s] = d * 1.25f;
        }
        float mx = lg[0];
#pragma unroll
        for (int s = 1; s < Ks; s++) mx = fmaxf(mx, lg[s]);
        float den = 0.f, ex[Ks];
#pragma unroll
        for (int s = 0; s < Ks; s++) { ex[s] = expf(lg[s] - mx); den += ex[s]; }
        float inv = 1.f / den;
#pragma unroll
        for (int s = 0; s < Ks; s++) att_s[s][tid] = ex[s] * inv;
        __syncthreads();
        for (int n = 0; n < 64; n++) {
            float v = vt[n * 65 + tid];
#pragma unroll
            for (int s = 0; s < Ks; s++) pacc[s] = fmaf(att_s[s][n], v, pacc[s]);
        }
        if (tid < Ks) {
            float s0 = 0.f;
            for (int n = 0; n < 64; n++) s0 += att_s[tid][n];
            asum_acc += s0;
        }
    }
#pragma unroll
    for (int s = 0; s < Ks; s++)
        g_Ppart[(((size_t)(b * NBLK) + blk) * Ks + s) * 64 + tid] = pacc[s];
    if (tid < Ks) g_attsum[(b * NBLK + blk) * Ks + tid] = asum_acc;
}

// ---------------------------------------------------------------------------
__global__ __launch_bounds__(64)
void update_k(const float* __restrict__ wih, const float* __restrict__ whh,
              const float* __restrict__ bih, const float* __restrict__ bhh,
              const float* __restrict__ ug, const float* __restrict__ ub,
              const float* __restrict__ f1w, const float* __restrict__ f1b,
              const float* __restrict__ f2w, const float* __restrict__ f2b)
{
    __shared__ float upd_s[Ks][64];
    __shared__ float q_s[Ks][64];
    __shared__ float gi_s[Ks][192];
    __shared__ float gh_s[Ks][192];
    __shared__ float h_s[Ks][64];
    __shared__ float hn_s[Ks][64];
    __shared__ float a_s[Ks][16];
    __shared__ float stats[Ks][2];
    const int tid = threadIdx.x, b = blockIdx.x;
    float vs = g_valsum[b * 64 + tid];
    for (int s = 0; s < Ks; s++) {
        float p = 0.f, asum = 0.f;
        for (int blk = 0; blk < NBLK; blk++) {
            p    += g_Ppart[(((size_t)(b * NBLK) + blk) * Ks + s) * 64 + tid];
            asum += g_attsum[(b * NBLK + blk) * Ks + s];
        }
        upd_s[s][tid] = p / asum + 1e-8f * vs;
        q_s[s][tid]   = g_q[(b * Ks + s) * 64 + tid];
    }
    __syncthreads();
    for (int e = tid; e < Ks * 192; e += 64) {
        int s = e / 192, j = e - s * 192;
        float si = bih[j], sh = bhh[j];
        const float* wi = &wih[j * 64];
        const float* wh = &whh[j * 64];
        for (int k = 0; k < 64; k++) {
            si = fmaf(upd_s[s][k], wi[k], si);
            sh = fmaf(q_s[s][k],   wh[k], sh);
        }
        gi_s[s][j] = si; gh_s[s][j] = sh;
    }
    __syncthreads();
    for (int s = 0; s < Ks; s++) {
        float r  = 1.f / (1.f + expf(-(gi_s[s][tid] + gh_s[s][tid])));
        float z  = 1.f / (1.f + expf(-(gi_s[s][64 + tid] + gh_s[s][64 + tid])));
        float nn = tanhf(gi_s[s][128 + tid] + r * gh_s[s][128 + tid]);
        h_s[s][tid] = (1.f - z) * nn + z * q_s[s][tid];
    }
    __syncthreads();
    if (tid < Ks) {
        float sm = 0.f, s2 = 0.f;
        for (int k = 0; k < 64; k++) { float v = h_s[tid][k]; sm += v; s2 += v * v; }
        float m = sm * (1.f / 64.f);
        stats[tid][0] = m;
        stats[tid][1] = rsqrtf(s2 * (1.f / 64.f) - m * m + 1e-5f);
    }
    __syncthreads();
    for (int s = 0; s < Ks; s++)
        hn_s[s][tid] = (h_s[s][tid] - stats[s][0]) * stats[s][1] * ug[tid] + ub[tid];
    __syncthreads();
    for (int e = tid; e < Ks * 16; e += 64) {
        int s = e >> 4, i = e & 15;
        float a = f1b[i];
        for (int k = 0; k < 64; k++) a = fmaf(hn_s[s][k], f1w[i * 64 + k], a);
        a_s[s][i] = fmaxf(a, 0.f);
    }
    __syncthreads();
    for (int s = 0; s < Ks; s++) {
        float f = f2b[tid];
#pragma unroll
        for (int i = 0; i < 16; i++) f = fmaf(a_s[s][i], f2w[tid * 16 + i], f);
        g_q[(b * Ks + s) * 64 + tid] = h_s[s][tid] + f;
    }
}

__global__ __launch_bounds__(64)
void final_k(const float* __restrict__ fw, const float* __restrict__ fb,
             float* __restrict__ out)
{
    const int b = blockIdx.x, tid = threadIdx.x;
    if (tid < Ks * 2) {
        int s = tid >> 1, k2 = tid & 1;
        float p = fb[k2];
        for (int k = 0; k < 64; k++)
            p = fmaf(g_q[(b * Ks + s) * 64 + k], fw[k2 * 64 + k], p);
        out[(b * Ks + s) * 2 + k2] = p;
    }
    for (int e = tid; e < Ks * 64; e += 64)
        out[Bn * Ks * 2 + b * Ks * 64 + e] = g_q[b * Ks * 64 + e];
}

// ---------------------------------------------------------------------------
extern "C" void kernel_launch(void* const* d_in, const int* in_sizes, int n_in,
                              void* d_out, int out_size)
{
    if (n_in < 28) return;
    static const int exp_sizes[28] = {
        2621440, 14336, 8000, 64, 102400, 64, 102400, 64,
        64, 64, 64, 64, 64, 64, 4096, 64, 4096, 64,
        12288, 12288, 192, 192, 1024, 16, 1024, 64, 128, 2
    };
    for (int i = 0; i < 28; i++)
        if (in_sizes[i] != exp_sizes[i]) {
            fprintf(stderr, "[slotattn] ABORT size[%d]=%d\n", i, in_sizes[i]);
            return;
        }

    const float* data = (const float*)d_in[0];
    const float* slots= (const float*)d_in[1];
    const float* c1w  = (const float*)d_in[2];
    const float* c1b  = (const float*)d_in[3];
    const float* c2w  = (const float*)d_in[4];
    const float* c2b  = (const float*)d_in[5];
    const float* c3w  = (const float*)d_in[6];
    const float* c3b  = (const float*)d_in[7];
    const float* dNg  = (const float*)d_in[8];
    const float* dNb  = (const float*)d_in[9];
    const float* qNg  = (const float*)d_in[10];
    const float* qNb  = (const float*)d_in[11];
    const float* uNg  = (const float*)d_in[12];
    const float* uNb  = (const float*)d_in[13];
    const float* toKw = (const float*)d_in[14];
    const float* toKb = (const float*)d_in[15];
    const float* toVw = (const float*)d_in[16];
    const float* toVb = (const float*)d_in[17];
    const float* gwih = (const float*)d_in[18];
    const float* gwhh = (const float*)d_in[19];
    const float* gbih = (const float*)d_in[20];
    const float* gbhh = (const float*)d_in[21];
    const float* f1w  = (const float*)d_in[22];
    const float* f1b  = (const float*)d_in[23];
    const float* f2w  = (const float*)d_in[24];
    const float* f2b  = (const float*)d_in[25];
    const float* fnw  = (const float*)d_in[26];
    const float* fnb  = (const float*)d_in[27];

    // dynamic smem: dup-input float2 + weights
    const int smem1 = 5 * 432 * 8 + 5 * 25 * 64 * 4;   // 49280 (>48K -> attr)
    const int smem2 = 4 * 432 * 8 + 4 * 25 * 64 * 4;   // 39424
    cudaFuncSetAttribute(conv5x5<5,  5, true,  0>, cudaFuncAttributeMaxDynamicSharedMemorySize, smem1);
    cudaFuncSetAttribute(conv5x5<64, 4, true,  1>, cudaFuncAttributeMaxDynamicSharedMemorySize, smem2);
    cudaFuncSetAttribute(conv5x5<64, 4, false, 2>, cudaFuncAttributeMaxDynamicSharedMemorySize, smem2);

    dim3 cgrid(4, Bn * 16, 1);
    conv5x5<5,  5, true,  0><<<cgrid, 256, smem1>>>(data, c1w, c1b);
    conv5x5<64, 4, true,  1><<<cgrid, 256, smem2>>>(nullptr, c2w, c2b);
    conv5x5<64, 4, false, 2><<<cgrid, 256, smem2>>>(nullptr, c3w, c3b);

    ln_transpose<<<Bn * 512, 256>>>(dNg, dNb);
    kv_gemm<<<dim3(512, Bn), 256>>>(toKw, toKb, toVw, toVb);
    valsum_k<<<Bn, 256>>>();
    copy_q<<<(Bn * Ks * Qd + 255) / 256, 256>>>(slots, Bn * Ks * Qd);
    for (int it = 0; it < 3; it++) {
        attn_k<<<dim3(NBLK, Bn), 64>>>(qNg, qNb);
        update_k<<<Bn, 64>>>(gwih, gwhh, gbih, gbhh, uNg, uNb, f1w, f1b, f2w, f2b);
    }
    final_k<<<Bn, 64>>>(fnw, fnb, (float*)d_out);
}

// round 12
// speedup vs baseline: 1.7282x; 1.7282x over previous
#include <cuda_runtime.h>
#include <cuda_bf16.h>
#include <math.h>
#include <cstdio>
#include <cstdint>

#define Bn 32
#define HID 64
#define Npix 16384
#define Ks 7
#define Qd 64
#define NBLK 64
#define PROW 72
#define PBUF (136*PROW)

__device__ float g_buf1[(size_t)Bn * HID * Npix];
__device__ float g_buf2[(size_t)Bn * HID * Npix];
__device__ float g_keys[(size_t)Bn * Npix * Qd];
__device__ float g_vals[(size_t)Bn * Npix * Qd];
__device__ float g_valsum[Bn * Qd];
__device__ float g_q[Bn * Ks * Qd];
__device__ float g_Ppart[(size_t)Bn * NBLK * Ks * Qd];
__device__ float g_attsum[Bn * NBLK * Ks];
__device__ __align__(16) unsigned char g_wpack[921600]; // c1@0, c2@102400, c3@512000

__device__ __forceinline__ uint32_t smem_u32(const void* p) {
    uint32_t a;
    asm("{ .reg .u64 t; cvta.to.shared.u64 t, %1; cvt.u32.u64 %0, t; }" : "=r"(a) : "l"(p));
    return a;
}
__device__ __forceinline__ void ldmx2(uint32_t& r0, uint32_t& r1, uint32_t a) {
    asm volatile("ldmatrix.sync.aligned.m8n8.x2.shared.b16 {%0,%1}, [%2];"
                 : "=r"(r0), "=r"(r1) : "r"(a));
}
__device__ __forceinline__ void mma16816(float* d, uint32_t a0, uint32_t a1, uint32_t a2,
                                         uint32_t a3, uint32_t b0, uint32_t b1) {
    asm volatile("mma.sync.aligned.m16n8k16.row.col.f32.bf16.bf16.f32 "
                 "{%0,%1,%2,%3}, {%4,%5,%6,%7}, {%8,%9}, {%0,%1,%2,%3};"
                 : "+f"(d[0]), "+f"(d[1]), "+f"(d[2]), "+f"(d[3])
                 : "r"(a0), "r"(a1), "r"(a2), "r"(a3), "r"(b0), "r"(b1));
}

// pack A fragments: per (step, chunk, mtile, split): 32 lanes x 16B
__global__ void prep_w(const float* __restrict__ c1w, const float* __restrict__ c2w,
                       const float* __restrict__ c3w)
{
    const int step = blockIdx.x, conv = blockIdx.y;
    const int ky = step / 5, kx = step - ky * 5;
    const float* w = conv == 0 ? c1w : (conv == 1 ? c2w : c3w);
    const int CIR = conv == 0 ? 5 : 64, CH = conv == 0 ? 1 : 4;
    const size_t base = conv == 0 ? 0 : (conv == 1 ? 102400 : 512000);
    for (int u = threadIdx.x; u < CH * 256; u += 256) {
        int lane = u & 31, s = (u >> 5) & 1, m = (u >> 6) & 3, c = u >> 8;
        int r = lane >> 2, cq = (lane & 3) * 2;
        uint32_t q[4];
        for (int jj = 0; jj < 4; jj++) {
            unsigned short hw[2];
            for (int k2 = 0; k2 < 2; k2++) {
                int j = jj * 2 + k2;
                int co = m * 16 + r + ((j >> 1) & 1) * 8;
                int ci = c * 16 + cq + (j & 1) + (j >> 2) * 8;
                float v = (ci < CIR) ? w[(((size_t)co * CIR + ci) * 5 + ky) * 5 + kx] : 0.f;
                __nv_bfloat16 hv = __float2bfloat16(v);
                __nv_bfloat16 ov = s ? __float2bfloat16(v - __bfloat162float(hv)) : hv;
                hw[k2] = *(unsigned short*)&ov;
            }
            q[jj] = (uint32_t)hw[0] | ((uint32_t)hw[1] << 16);
        }
        *(uint4*)(g_wpack + base + (size_t)(((step * CH + c) * 4 + m) * 2 + s) * 512 + lane * 16)
            = make_uint4(q[0], q[1], q[2], q[3]);
    }
}

template <int CIR, int CHUNKS, bool RELU, int DIR>
__global__ __launch_bounds__(256, 1)
void conv_mma(const float* __restrict__ ext_in, const float* __restrict__ bias, int wofs)
{
    extern __shared__ char sm[];
    constexpr int ABYTES = CHUNKS * 4096, NA = ABYTES / 4096, CISTG = CHUNKS * 16;
    __nv_bfloat16* P = (__nv_bfloat16*)sm;                   // [rb3][hi/lo][PBUF]
    char* Ab = sm + 3 * 2 * PBUF * 2;
    float* bias_s = (float*)(Ab + 2 * ABYTES);

    const int tid = threadIdx.x, lane = tid & 31, w = tid >> 5;
    const int mg = w & 1, ng = (w >> 1) & 1, yg = w >> 2;
    const int b = blockIdx.y, y0 = blockIdx.x * 2;
    const int il = lane & 7, hf = (lane >> 3) & 1;
    const float* src = (DIR == 0) ? ext_in + (size_t)b * CIR * Npix
                     : ((DIR == 1 ? g_buf1 : g_buf2) + ((size_t)b << 20));
    float* dst = (DIR == 1) ? g_buf2 : g_buf1;
    const uint32_t sbase = smem_u32(sm);

    if (tid < 64) bias_s[tid] = bias[tid];

    auto stage_row = [&](int j) {
        int ry = y0 - 2 + j;
        __nv_bfloat16* ph = P + (j % 3) * 2 * PBUF;
        __nv_bfloat16* pl = ph + PBUF;
        bool rok = (unsigned)ry < 128u;
        for (int e = tid; e < CISTG * 136; e += 256) {
            int ci = e / 136, i = e - ci * 136, x = i - 2;
            float v = 0.f;
            if (rok && (unsigned)x < 128u && ci < CIR)
                v = src[((size_t)ci << 14) + (ry << 7) + x];
            __nv_bfloat16 hv = __float2bfloat16(v);
            ph[i * PROW + ci] = hv;
            pl[i * PROW + ci] = __float2bfloat16(v - __bfloat162float(hv));
        }
    };

    stage_row(0); stage_row(1);
    {
        const uint4* s = (const uint4*)(g_wpack + wofs);
        uint4* d = (uint4*)Ab;
#pragma unroll
        for (int k = 0; k < NA; k++) d[tid + k * 256] = s[tid + k * 256];
    }
    __syncthreads();

    float acc[2][8][4];
#pragma unroll
    for (int mi = 0; mi < 2; mi++)
#pragma unroll
        for (int ni = 0; ni < 8; ni++)
#pragma unroll
            for (int k = 0; k < 4; k++) acc[mi][ni][k] = 0.f;

    for (int step = 0; step < 25; step++) {
        const int ky = step / 5, kx = step - ky * 5;
        uint4 tA[NA];
        if (step + 1 < 25) {
            const uint4* s = (const uint4*)(g_wpack + wofs + (size_t)(step + 1) * ABYTES);
#pragma unroll
            for (int k = 0; k < NA; k++) tA[k] = s[tid + k * 256];
        }
        if (kx == 0 && ky + 2 <= 5) stage_row(ky + 2);

        const char* A0 = Ab + (step & 1) * ABYTES;
        const uint32_t pb = sbase + ((ky + yg) % 3) * (2 * PBUF * 2);
#pragma unroll
        for (int c = 0; c < CHUNKS; c++) {
            uint4 AH[2], AL[2];
#pragma unroll
            for (int mi = 0; mi < 2; mi++) {
                int mt = mg * 2 + mi;
                AH[mi] = *((const uint4*)(A0 + ((c * 4 + mt) * 2 + 0) * 512) + lane);
                AL[mi] = *((const uint4*)(A0 + ((c * 4 + mt) * 2 + 1) * 512) + lane);
            }
#pragma unroll
            for (int ni = 0; ni < 8; ni++) {
                uint32_t bh0, bh1, bl0, bl1;
                uint32_t ra = pb + (uint32_t)(ng * 64 + ni * 8 + kx + il) * 144 + c * 32 + hf * 16;
                ldmx2(bh0, bh1, ra);
                ldmx2(bl0, bl1, ra + PBUF * 2);
#pragma unroll
                for (int mi = 0; mi < 2; mi++) {
                    mma16816(acc[mi][ni], AH[mi].x, AH[mi].y, AH[mi].z, AH[mi].w, bh0, bh1);
                    mma16816(acc[mi][ni], AH[mi].x, AH[mi].y, AH[mi].z, AH[mi].w, bl0, bl1);
                    mma16816(acc[mi][ni], AL[mi].x, AL[mi].y, AL[mi].z, AL[mi].w, bh0, bh1);
                }
            }
        }
        if (step + 1 < 25) {
            uint4* d = (uint4*)(Ab + ((step + 1) & 1) * ABYTES);
#pragma unroll
            for (int k = 0; k < NA; k++) d[tid + k * 256] = tA[k];
        }
        __syncthreads();
    }

    const int r = lane >> 2, cq = (lane & 3) * 2, y = y0 + yg;
#pragma unroll
    for (int mi = 0; mi < 2; mi++) {
        int co = mg * 32 + mi * 16;
        float b0 = bias_s[co + r], b1 = bias_s[co + r + 8];
        float* o0 = dst + ((size_t)(b * 64 + co + r) << 14) + (y << 7);
        float* o1 = dst + ((size_t)(b * 64 + co + r + 8) << 14) + (y << 7);
#pragma unroll
        for (int ni = 0; ni < 8; ni++) {
            int px = ng * 64 + ni * 8 + cq;
            float v0 = acc[mi][ni][0] + b0, v1 = acc[mi][ni][1] + b0;
            float v2 = acc[mi][ni][2] + b1, v3 = acc[mi][ni][3] + b1;
            if (RELU) {
                v0 = fmaxf(v0, 0.f); v1 = fmaxf(v1, 0.f);
                v2 = fmaxf(v2, 0.f); v3 = fmaxf(v3, 0.f);
            }
            *(float2*)(o0 + px) = make_float2(v0, v1);
            *(float2*)(o1 + px) = make_float2(v2, v3);
        }
    }
}

__global__ __launch_bounds__(256)
void ln_transpose(const float* __restrict__ g, const float* __restrict__ bta)
{
    __shared__ float t[HID * 33];
    __shared__ float mean_s[32], rstd_s[32];
    const int tid = threadIdx.x;
    const int b = blockIdx.x >> 9, n0 = (blockIdx.x & 511) * 32;
    for (int e = tid; e < HID * 32; e += 256) {
        int c = e >> 5, j = e & 31;
        t[c * 33 + j] = g_buf1[((size_t)(b * HID + c) << 14) + n0 + j];
    }
    __syncthreads();
    if (tid < 32) {
        float s = 0.f, s2 = 0.f;
        for (int c = 0; c < HID; c++) { float v = t[c * 33 + tid]; s += v; s2 += v * v; }
        float m = s * (1.f / HID);
        mean_s[tid] = m;
        rstd_s[tid] = rsqrtf(s2 * (1.f / HID) - m * m + 1e-5f);
    }
    __syncthreads();
    for (int e = tid; e < HID * 32; e += 256) {
        int j = e >> 6, c = e & (HID - 1);
        float v = (t[c * 33 + j] - mean_s[j]) * rstd_s[j] * g[c] + bta[c];
        g_buf2[((size_t)(b * Npix + n0 + j) << 6) + c] = v;
    }
}

__global__ __launch_bounds__(256)
void kv_gemm(const float* __restrict__ wk, const float* __restrict__ bk,
             const float* __restrict__ wv, const float* __restrict__ bv)
{
    __shared__ float a_s[32 * 37];
    __shared__ float w_s[32 * 128];
    const int tid = threadIdx.x;
    const int b = blockIdx.y, n0 = blockIdx.x * 32;
    const int og = tid & 31, ng = tid >> 5;
    float acc[4][4];
#pragma unroll
    for (int i = 0; i < 4; i++)
#pragma unroll
        for (int j = 0; j < 4; j++) acc[i][j] = 0.f;
    for (int kc = 0; kc < HID; kc += 32) {
        __syncthreads();
        for (int e = tid; e < 1024; e += 256) {
            int n = e >> 5, k = e & 31;
            a_s[n * 37 + k] = g_buf2[((size_t)(b * Npix + n0 + n) << 6) + kc + k];
        }
        for (int e = tid; e < 4096; e += 256) {
            int k = e >> 7, o = e & 127;
            w_s[e] = (o < 64) ? wk[o * HID + kc + k] : wv[(o - 64) * HID + kc + k];
        }
        __syncthreads();
#pragma unroll 8
        for (int k = 0; k < 32; k++) {
            float av[4];
#pragma unroll
            for (int i = 0; i < 4; i++) av[i] = a_s[(ng * 4 + i) * 37 + k];
            float4 w4 = *(const float4*)&w_s[k * 128 + og * 4];
            float bw[4] = {w4.x, w4.y, w4.z, w4.w};
#pragma unroll
            for (int i = 0; i < 4; i++)
#pragma unroll
                for (int j = 0; j < 4; j++)
                    acc[i][j] = fmaf(av[i], bw[j], acc[i][j]);
        }
    }
#pragma unroll
    for (int i = 0; i < 4; i++) {
        int n = n0 + ng * 4 + i;
#pragma unroll
        for (int j = 0; j < 4; j++) {
            int o = og * 4 + j;
            if (o < 64) g_keys[((size_t)(b * Npix + n) << 6) + o] = acc[i][j] + bk[o];
            else        g_vals[((size_t)(b * Npix + n) << 6) + (o - 64)] = acc[i][j] + bv[o - 64];
        }
    }
}

__global__ __launch_bounds__(256)
void valsum_k()
{
    __shared__ float p_s[4][64];
    const int tid = threadIdx.x, b = blockIdx.x;
    const int q = tid & 63, part = tid >> 6;
    float s = 0.f;
    for (int n = part; n < Npix; n += 4)
        s += g_vals[((size_t)(b * Npix + n) << 6) + q];
    p_s[part][q] = s;
    __syncthreads();
    if (tid < 64)
        g_valsum[b * 64 + tid] = p_s[0][tid] + p_s[1][tid] + p_s[2][tid] + p_s[3][tid];
}

__global__ void copy_q(const float* __restrict__ src, int n)
{
    int i = blockIdx.x * 256 + threadIdx.x;
    if (i < n) g_q[i] = src[i];
}

__global__ __launch_bounds__(64)
void attn_k(const float* __restrict__ qg, const float* __restrict__ qb)
{
    __shared__ float kt[64 * 65];
    __shared__ float vt[64 * 65];
    __shared__ float qn_s[Ks][64];
    __shared__ float att_s[Ks][65];
    __shared__ float mr[Ks][2];
    const int tid = threadIdx.x;
    const int b = blockIdx.y, blk = blockIdx.x;
    for (int s = 0; s < Ks; s++) qn_s[s][tid] = g_q[(b * Ks + s) * 64 + tid];
    __syncthreads();
    if (tid < Ks) {
        float sm = 0.f, s2 = 0.f;
        for (int k = 0; k < 64; k++) { float v = qn_s[tid][k]; sm += v; s2 += v * v; }
        float m = sm * (1.f / 64.f);
        mr[tid][0] = m;
        mr[tid][1] = rsqrtf(s2 * (1.f / 64.f) - m * m + 1e-5f);
    }
    __syncthreads();
    for (int s = 0; s < Ks; s++)
        qn_s[s][tid] = (qn_s[s][tid] - mr[s][0]) * mr[s][1] * qg[tid] + qb[tid];
    float pacc[Ks];
#pragma unroll
    for (int s = 0; s < Ks; s++) pacc[s] = 0.f;
    float asum_acc = 0.f;
    const int nbase = blk * (Npix / NBLK);
    for (int t = 0; t < (Npix / NBLK) / 64; t++) {
        int n0 = nbase + t * 64;
        __syncthreads();
        for (int e = tid; e < 4096; e += 64) {
            int n = e >> 6, qq = e & 63;
            kt[n * 65 + qq] = g_keys[((size_t)(b * Npix + n0 + n) << 6) + qq];
            vt[n * 65 + qq] = g_vals[((size_t)(b * Npix + n0 + n) << 6) + qq];
        }
        __syncthreads();
        float lg[Ks];
#pragma unroll
        for (int s = 0; s < Ks; s++) {
            float d = 0.f;
            for (int k = 0; k < 64; k++) d = fmaf(qn_s[s][k], kt[tid * 65 + k], d);
            lg[s] = d * 1.25f;
        }
        float mx = lg[0];
#pragma unroll
        for (int s = 1; s < Ks; s++) mx = fmaxf(mx, lg[s]);
        float den = 0.f, ex[Ks];
#pragma unroll
        for (int s = 0; s < Ks; s++) { ex[s] = expf(lg[s] - mx); den += ex[s]; }
        float inv = 1.f / den;
#pragma unroll
        for (int s = 0; s < Ks; s++) att_s[s][tid] = ex[s] * inv;
        __syncthreads();
        for (int n = 0; n < 64; n++) {
            float v = vt[n * 65 + tid];
#pragma unroll
            for (int s = 0; s < Ks; s++) pacc[s] = fmaf(att_s[s][n], v, pacc[s]);
        }
        if (tid < Ks) {
            float s0 = 0.f;
            for (int n = 0; n < 64; n++) s0 += att_s[tid][n];
            asum_acc += s0;
        }
    }
#pragma unroll
    for (int s = 0; s < Ks; s++)
        g_Ppart[(((size_t)(b * NBLK) + blk) * Ks + s) * 64 + tid] = pacc[s];
    if (tid < Ks) g_attsum[(b * NBLK + blk) * Ks + tid] = asum_acc;
}

__global__ __launch_bounds__(64)
void update_k(const float* __restrict__ wih, const float* __restrict__ whh,
              const float* __restrict__ bih, const float* __restrict__ bhh,
              const float* __restrict__ ug, const float* __restrict__ ub,
              const float* __restrict__ f1w, const float* __restrict__ f1b,
              const float* __restrict__ f2w, const float* __restrict__ f2b)
{
    __shared__ float upd_s[Ks][64];
    __shared__ float q_s[Ks][64];
    __shared__ float gi_s[Ks][192];
    __shared__ float gh_s[Ks][192];
    __shared__ float h_s[Ks][64];
    __shared__ float hn_s[Ks][64];
    __shared__ float a_s[Ks][16];
    __shared__ float stats[Ks][2];
    const int tid = threadIdx.x, b = blockIdx.x;
    float vs = g_valsum[b * 64 + tid];
    for (int s = 0; s < Ks; s++) {
        float p = 0.f, asum = 0.f;
        for (int blk = 0; blk < NBLK; blk++) {
            p    += g_Ppart[(((size_t)(b * NBLK) + blk) * Ks + s) * 64 + tid];
            asum += g_attsum[(b * NBLK + blk) * Ks + s];
        }
        upd_s[s][tid] = p / asum + 1e-8f * vs;
        q_s[s][tid]   = g_q[(b * Ks + s) * 64 + tid];
    }
    __syncthreads();
    for (int e = tid; e < Ks * 192; e += 64) {
        int s = e / 192, j = e - s * 192;
        float si = bih[j], sh = bhh[j];
        const float* wi = &wih[j * 64];
        const float* wh = &whh[j * 64];
        for (int k = 0; k < 64; k++) {
            si = fmaf(upd_s[s][k], wi[k], si);
            sh = fmaf(q_s[s][k],   wh[k], sh);
        }
        gi_s[s][j] = si; gh_s[s][j] = sh;
    }
    __syncthreads();
    for (int s = 0; s < Ks; s++) {
        float r  = 1.f / (1.f + expf(-(gi_s[s][tid] + gh_s[s][tid])));
        float z  = 1.f / (1.f + expf(-(gi_s[s][64 + tid] + gh_s[s][64 + tid])));
        float nn = tanhf(gi_s[s][128 + tid] + r * gh_s[s][128 + tid]);
        h_s[s][tid] = (1.f - z) * nn + z * q_s[s][tid];
    }
    __syncthreads();
    if (tid < Ks) {
        float sm = 0.f, s2 = 0.f;
        for (int k = 0; k < 64; k++) { float v = h_s[tid][k]; sm += v; s2 += v * v; }
        float m = sm * (1.f / 64.f);
        stats[tid][0] = m;
        stats[tid][1] = rsqrtf(s2 * (1.f / 64.f) - m * m + 1e-5f);
    }
    __syncthreads();
    for (int s = 0; s < Ks; s++)
        hn_s[s][tid] = (h_s[s][tid] - stats[s][0]) * stats[s][1] * ug[tid] + ub[tid];
    __syncthreads();
    for (int e = tid; e < Ks * 16; e += 64) {
        int s = e >> 4, i = e & 15;
        float a = f1b[i];
        for (int k = 0; k < 64; k++) a = fmaf(hn_s[s][k], f1w[i * 64 + k], a);
        a_s[s][i] = fmaxf(a, 0.f);
    }
    __syncthreads();
    for (int s = 0; s < Ks; s++) {
        float f = f2b[tid];
#pragma unroll
        for (int i = 0; i < 16; i++) f = fmaf(a_s[s][i], f2w[tid * 16 + i], f);
        g_q[(b * Ks + s) * 64 + tid] = h_s[s][tid] + f;
    }
}

__global__ __launch_bounds__(64)
void final_k(const float* __restrict__ fw, const float* __restrict__ fb,
             float* __restrict__ out)
{
    const int b = blockIdx.x, tid = threadIdx.x;
    if (tid < Ks * 2) {
        int s = tid >> 1, k2 = tid & 1;
        float p = fb[k2];
        for (int k = 0; k < 64; k++)
            p = fmaf(g_q[(b * Ks + s) * 64 + k], fw[k2 * 64 + k], p);
        out[(b * Ks + s) * 2 + k2] = p;
    }
    for (int e = tid; e < Ks * 64; e += 64)
        out[Bn * Ks * 2 + b * Ks * 64 + e] = g_q[b * Ks * 64 + e];
}

extern "C" void kernel_launch(void* const* d_in, const int* in_sizes, int n_in,
                              void* d_out, int out_size)
{
    if (n_in < 28) return;
    static const int exp_sizes[28] = {
        2621440, 14336, 8000, 64, 102400, 64, 102400, 64,
        64, 64, 64, 64, 64, 64, 4096, 64, 4096, 64,
        12288, 12288, 192, 192, 1024, 16, 1024, 64, 128, 2
    };
    for (int i = 0; i < 28; i++)
        if (in_sizes[i] != exp_sizes[i]) {
            fprintf(stderr, "[slotattn] ABORT size[%d]=%d\n", i, in_sizes[i]);
            return;
        }
    const float* data = (const float*)d_in[0];
    const float* slots= (const float*)d_in[1];
    const float* c1w  = (const float*)d_in[2];
    const float* c1b  = (const float*)d_in[3];
    const float* c2w  = (const float*)d_in[4];
    const float* c2b  = (const float*)d_in[5];
    const float* c3w  = (const float*)d_in[6];
    const float* c3b  = (const float*)d_in[7];
    const float* dNg  = (const float*)d_in[8];
    const float* dNb  = (const float*)d_in[9];
    const float* qNg  = (const float*)d_in[10];
    const float* qNb  = (const float*)d_in[11];
    const float* uNg  = (const float*)d_in[12];
    const float* uNb  = (const float*)d_in[13];
    const float* toKw = (const float*)d_in[14];
    const float* toKb = (const float*)d_in[15];
    const float* toVw = (const float*)d_in[16];
    const float* toVb = (const float*)d_in[17];
    const float* gwih = (const float*)d_in[18];
    const float* gwhh = (const float*)d_in[19];
    const float* gbih = (const float*)d_in[20];
    const float* gbhh = (const float*)d_in[21];
    const float* f1w  = (const float*)d_in[22];
    const float* f1b  = (const float*)d_in[23];
    const float* f2w  = (const float*)d_in[24];
    const float* f2b  = (const float*)d_in[25];
    const float* fnw  = (const float*)d_in[26];
    const float* fnb  = (const float*)d_in[27];

    const int PATCHB = 3 * 2 * PBUF * 2;               // 117504
    const int smem1 = PATCHB + 2 * 4096 + 256;         // conv1
    const int smem2 = PATCHB + 2 * 16384 + 256;        // conv2/3
    cudaFuncSetAttribute(conv_mma<5, 1, true, 0>,  cudaFuncAttributeMaxDynamicSharedMemorySize, smem1);
    cudaFuncSetAttribute(conv_mma<64, 4, true, 1>, cudaFuncAttributeMaxDynamicSharedMemorySize, smem2);
    cudaFuncSetAttribute(conv_mma<64, 4, false, 2>,cudaFuncAttributeMaxDynamicSharedMemorySize, smem2);

    prep_w<<<dim3(25, 3), 256>>>(c1w, c2w, c3w);
    dim3 cg(64, Bn);
    conv_mma<5, 1, true, 0><<<cg, 256, smem1>>>(data, c1b, 0);
    conv_mma<64, 4, true, 1><<<cg, 256, smem2>>>(nullptr, c2b, 102400);
    conv_mma<64, 4, false, 2><<<cg, 256, smem2>>>(nullptr, c3b, 512000);

    ln_transpose<<<Bn * 512, 256>>>(dNg, dNb);
    kv_gemm<<<dim3(512, Bn), 256>>>(toKw, toKb, toVw, toVb);
    valsum_k<<<Bn, 256>>>();
    copy_q<<<(Bn * Ks * Qd + 255) / 256, 256>>>(slots, Bn * Ks * Qd);
    for (int it = 0; it < 3; it++) {
        attn_k<<<dim3(NBLK, Bn), 64>>>(qNg, qNb);
        update_k<<<Bn, 64>>>(gwih, gwhh, gbih, gbhh, uNg, uNb, f1w, f1b, f2w, f2b);
    }
    final_k<<<Bn, 64>>>(fnw, fnb, (float*)d_out);
}

// round 14
// speedup vs baseline: 1.8524x; 1.0719x over previous
#include <cuda_runtime.h>
#include <cuda_bf16.h>
#include <math.h>
#include <cstdio>
#include <cstdint>

#define Bn 32
#define HID 64
#define Npix 16384
#define Ks 7
#define Qd 64
#define NBLK 64
#define PROW 72
#define PBUF (136*PROW)

__device__ float g_buf1[(size_t)Bn * HID * Npix];
__device__ float g_buf2[(size_t)Bn * HID * Npix];
__device__ float g_keys[(size_t)Bn * Npix * Qd];
__device__ float g_vals[(size_t)Bn * Npix * Qd];
__device__ float g_valsum[Bn * Qd];
__device__ float g_vsum_part[(size_t)Bn * 512 * 64];
__device__ float g_q[Bn * Ks * Qd];
__device__ float g_Ppart[(size_t)Bn * NBLK * Ks * Qd];
__device__ float g_attsum[Bn * NBLK * Ks];
__device__ __align__(16) unsigned char g_wpack[921600]; // c1@0, c2@102400, c3@512000

__device__ __forceinline__ uint32_t smem_u32(const void* p) {
    uint32_t a;
    asm("{ .reg .u64 t; cvta.to.shared.u64 t, %1; cvt.u32.u64 %0, t; }" : "=r"(a) : "l"(p));
    return a;
}
__device__ __forceinline__ void ldmx2(uint32_t& r0, uint32_t& r1, uint32_t a) {
    asm volatile("ldmatrix.sync.aligned.m8n8.x2.shared.b16 {%0,%1}, [%2];"
                 : "=r"(r0), "=r"(r1) : "r"(a));
}
__device__ __forceinline__ void mma16816(float* d, uint32_t a0, uint32_t a1, uint32_t a2,
                                         uint32_t a3, uint32_t b0, uint32_t b1) {
    asm volatile("mma.sync.aligned.m16n8k16.row.col.f32.bf16.bf16.f32 "
                 "{%0,%1,%2,%3}, {%4,%5,%6,%7}, {%8,%9}, {%0,%1,%2,%3};"
                 : "+f"(d[0]), "+f"(d[1]), "+f"(d[2]), "+f"(d[3])
                 : "r"(a0), "r"(a1), "r"(a2), "r"(a3), "r"(b0), "r"(b1));
}

__global__ void prep_w(const float* __restrict__ c1w, const float* __restrict__ c2w,
                       const float* __restrict__ c3w)
{
    const int step = blockIdx.x, conv = blockIdx.y;
    const int ky = step / 5, kx = step - ky * 5;
    const float* w = conv == 0 ? c1w : (conv == 1 ? c2w : c3w);
    const int CIR = conv == 0 ? 5 : 64, CH = conv == 0 ? 1 : 4;
    const size_t base = conv == 0 ? 0 : (conv == 1 ? 102400 : 512000);
    for (int u = threadIdx.x; u < CH * 256; u += 256) {
        int lane = u & 31, s = (u >> 5) & 1, m = (u >> 6) & 3, c = u >> 8;
        int r = lane >> 2, cq = (lane & 3) * 2;
        uint32_t q[4];
        for (int jj = 0; jj < 4; jj++) {
            unsigned short hw[2];
            for (int k2 = 0; k2 < 2; k2++) {
                int j = jj * 2 + k2;
                int co = m * 16 + r + ((j >> 1) & 1) * 8;
                int ci = c * 16 + cq + (j & 1) + (j >> 2) * 8;
                float v = (ci < CIR) ? w[(((size_t)co * CIR + ci) * 5 + ky) * 5 + kx] : 0.f;
                __nv_bfloat16 hv = __float2bfloat16(v);
                __nv_bfloat16 ov = s ? __float2bfloat16(v - __bfloat162float(hv)) : hv;
                hw[k2] = *(unsigned short*)&ov;
            }
            q[jj] = (uint32_t)hw[0] | ((uint32_t)hw[1] << 16);
        }
        *(uint4*)(g_wpack + base + (size_t)(((step * CH + c) * 4 + m) * 2 + s) * 512 + lane * 16)
            = make_uint4(q[0], q[1], q[2], q[3]);
    }
}

// 512 threads: 16 warps = mg(2) x ng(4) x yg(2); 4 ni per warp.
template <int CIR, int CHUNKS, bool RELU, int DIR>
__global__ __launch_bounds__(512, 1)
void conv_mma(const float* __restrict__ ext_in, const float* __restrict__ bias, int wofs)
{
    extern __shared__ char sm[];
    constexpr int ABYTES = CHUNKS * 4096, NAU = ABYTES / 16, CISTG = CHUNKS * 16;
    __nv_bfloat16* P = (__nv_bfloat16*)sm;
    char* Ab = sm + 3 * 2 * PBUF * 2;
    float* bias_s = (float*)(Ab + 2 * ABYTES);

    const int tid = threadIdx.x, lane = tid & 31, w = tid >> 5;
    const int mg = w & 1, ng = (w >> 1) & 3, yg = w >> 3;
    const int b = blockIdx.y, y0 = blockIdx.x * 2;
    const int il = lane & 7, hf = (lane >> 3) & 1;
    const float* src = (DIR == 0) ? ext_in + (size_t)b * CIR * Npix
                     : ((DIR == 1 ? g_buf1 : g_buf2) + ((size_t)b << 20));
    float* dst = (DIR == 1) ? g_buf2 : g_buf1;
    const uint32_t sbase = smem_u32(sm);

    if (tid < 64) bias_s[tid] = bias[tid];

    auto stage_row = [&](int j) {
        int ry = y0 - 2 + j;
        __nv_bfloat16* ph = P + (j % 3) * 2 * PBUF;
        __nv_bfloat16* pl = ph + PBUF;
        bool rok = (unsigned)ry < 128u;
        for (int e = tid; e < CISTG * 136; e += 512) {
            int ci = e / 136, i = e - ci * 136, x = i - 2;
            float v = 0.f;
            if (rok && (unsigned)x < 128u && ci < CIR)
                v = src[((size_t)ci << 14) + (ry << 7) + x];
            __nv_bfloat16 hv = __float2bfloat16(v);
            ph[i * PROW + ci] = hv;
            pl[i * PROW + ci] = __float2bfloat16(v - __bfloat162float(hv));
        }
    };

    stage_row(0); stage_row(1);
    for (int e = tid; e < NAU; e += 512)
        ((uint4*)Ab)[e] = ((const uint4*)(g_wpack + wofs))[e];
    __syncthreads();

    float acc[2][4][4];
#pragma unroll
    for (int mi = 0; mi < 2; mi++)
#pragma unroll
        for (int ni = 0; ni < 4; ni++)
#pragma unroll
            for (int k = 0; k < 4; k++) acc[mi][ni][k] = 0.f;

    for (int step = 0; step < 25; step++) {
        const int ky = step / 5, kx = step - ky * 5;
        uint4 tA[2];
        if (step + 1 < 25) {
            const uint4* s = (const uint4*)(g_wpack + wofs + (size_t)(step + 1) * ABYTES);
#pragma unroll
            for (int k = 0; k < 2; k++)
                if (tid + k * 512 < NAU) tA[k] = s[tid + k * 512];
        }
        if (kx == 0 && ky + 2 <= 5) stage_row(ky + 2);

        const char* A0 = Ab + (step & 1) * ABYTES;
        const uint32_t pb = sbase + ((ky + yg) % 3) * (2 * PBUF * 2);
#pragma unroll
        for (int c = 0; c < CHUNKS; c++) {
            uint4 AH[2], AL[2];
#pragma unroll
            for (int mi = 0; mi < 2; mi++) {
                int mt = mg * 2 + mi;
                AH[mi] = *((const uint4*)(A0 + ((c * 4 + mt) * 2 + 0) * 512) + lane);
                AL[mi] = *((const uint4*)(A0 + ((c * 4 + mt) * 2 + 1) * 512) + lane);
            }
#pragma unroll
            for (int ni = 0; ni < 4; ni++) {
                uint32_t bh0, bh1, bl0, bl1;
                uint32_t ra = pb + (uint32_t)(ng * 32 + ni * 8 + kx + il) * 144 + c * 32 + hf * 16;
                ldmx2(bh0, bh1, ra);
                ldmx2(bl0, bl1, ra + PBUF * 2);
#pragma unroll
                for (int mi = 0; mi < 2; mi++) {
                    mma16816(acc[mi][ni], AH[mi].x, AH[mi].y, AH[mi].z, AH[mi].w, bh0, bh1);
                    mma16816(acc[mi][ni], AH[mi].x, AH[mi].y, AH[mi].z, AH[mi].w, bl0, bl1);
                    mma16816(acc[mi][ni], AL[mi].x, AL[mi].y, AL[mi].z, AL[mi].w, bh0, bh1);
                }
            }
        }
        if (step + 1 < 25) {
            uint4* d = (uint4*)(Ab + ((step + 1) & 1) * ABYTES);
#pragma unroll
            for (int k = 0; k < 2; k++)
                if (tid + k * 512 < NAU) d[tid + k * 512] = tA[k];
        }
        __syncthreads();
    }

    const int r = lane >> 2, cq = (lane & 3) * 2, y = y0 + yg;
#pragma unroll
    for (int mi = 0; mi < 2; mi++) {
        int co = mg * 32 + mi * 16;
        float b0 = bias_s[co + r], b1 = bias_s[co + r + 8];
        float* o0 = dst + ((size_t)(b * 64 + co + r) << 14) + (y << 7);
        float* o1 = dst + ((size_t)(b * 64 + co + r + 8) << 14) + (y << 7);
#pragma unroll
        for (int ni = 0; ni < 4; ni++) {
            int px = ng * 32 + ni * 8 + cq;
            float v0 = acc[mi][ni][0] + b0, v1 = acc[mi][ni][1] + b0;
            float v2 = acc[mi][ni][2] + b1, v3 = acc[mi][ni][3] + b1;
            if (RELU) {
                v0 = fmaxf(v0, 0.f); v1 = fmaxf(v1, 0.f);
                v2 = fmaxf(v2, 0.f); v3 = fmaxf(v3, 0.f);
            }
            *(float2*)(o0 + px) = make_float2(v0, v1);
            *(float2*)(o1 + px) = make_float2(v2, v3);
        }
    }
}

// ---- fused LN + keys/vals GEMM + valsum partials (buf1 -> keys/vals) ----
__global__ __launch_bounds__(256)
void kv_ln_gemm(const float* __restrict__ g, const float* __restrict__ bta,
                const float* __restrict__ wk, const float* __restrict__ bk,
                const float* __restrict__ wv, const float* __restrict__ bv)
{
    __shared__ float a_s[32 * 65];
    __shared__ float w_s[64 * 128];
    __shared__ float mean_s[32], rstd_s[32];
    __shared__ float vs_s[8][64];
    const int tid = threadIdx.x;
    const int b = blockIdx.y, n0 = blockIdx.x * 32;
    const float* enc = g_buf1 + ((size_t)b << 20);

    for (int e = tid; e < 2048; e += 256) {
        int c = e >> 5, j = e & 31;
        a_s[j * 65 + c] = enc[((size_t)c << 14) + n0 + j];
    }
    for (int e = tid; e < 8192; e += 256) {
        int k = e >> 7, o = e & 127;
        w_s[e] = (o < 64) ? wk[o * 64 + k] : wv[(o - 64) * 64 + k];
    }
    __syncthreads();
    if (tid < 32) {
        float s = 0.f, s2 = 0.f;
        for (int c = 0; c < 64; c++) { float v = a_s[tid * 65 + c]; s += v; s2 += v * v; }
        float m = s * (1.f / 64.f);
        mean_s[tid] = m;
        rstd_s[tid] = rsqrtf(s2 * (1.f / 64.f) - m * m + 1e-5f);
    }
    __syncthreads();
    for (int e = tid; e < 2048; e += 256) {
        int j = e >> 6, c = e & 63;
        a_s[j * 65 + c] = (a_s[j * 65 + c] - mean_s[j]) * rstd_s[j] * g[c] + bta[c];
    }
    __syncthreads();

    const int og = tid & 31, ng = tid >> 5;
    float acc[4][4];
#pragma unroll
    for (int i = 0; i < 4; i++)
#pragma unroll
        for (int j = 0; j < 4; j++) acc[i][j] = 0.f;
#pragma unroll 8
    for (int k = 0; k < 64; k++) {
        float av[4];
#pragma unroll
        for (int i = 0; i < 4; i++) av[i] = a_s[(ng * 4 + i) * 65 + k];
        float4 w4 = *(const float4*)&w_s[k * 128 + og * 4];
        float bw[4] = {w4.x, w4.y, w4.z, w4.w};
#pragma unroll
        for (int i = 0; i < 4; i++)
#pragma unroll
            for (int j = 0; j < 4; j++)
                acc[i][j] = fmaf(av[i], bw[j], acc[i][j]);
    }
#pragma unroll
    for (int i = 0; i < 4; i++) {
        int n = n0 + ng * 4 + i;
#pragma unroll
        for (int j = 0; j < 4; j++) {
            int o = og * 4 + j;
            if (o < 64) g_keys[((size_t)(b * Npix + n) << 6) + o] = acc[i][j] + bk[o];
            else        g_vals[((size_t)(b * Npix + n) << 6) + (o - 64)] = acc[i][j] + bv[o - 64];
        }
    }
    if (og >= 16) {
#pragma unroll
        for (int j = 0; j < 4; j++) {
            int o = og * 4 + j - 64;
            vs_s[ng][o] = acc[0][j] + acc[1][j] + acc[2][j] + acc[3][j] + 4.f * bv[o];
        }
    }
    __syncthreads();
    if (tid < 64) {
        float s = 0.f;
        for (int p = 0; p < 8; p++) s += vs_s[p][tid];
        g_vsum_part[((size_t)b * 512 + blockIdx.x) * 64 + tid] = s;
    }
}

__global__ __launch_bounds__(64)
void valsum_reduce()
{
    const int b = blockIdx.x, q = threadIdx.x;
    float s = 0.f;
    for (int p = 0; p < 512; p++) s += g_vsum_part[((size_t)b * 512 + p) * 64 + q];
    g_valsum[b * 64 + q] = s;
}

__global__ void copy_q(const float* __restrict__ src, int n)
{
    int i = blockIdx.x * 256 + threadIdx.x;
    if (i < n) g_q[i] = src[i];
}

__global__ __launch_bounds__(64)
void attn_k(const float* __restrict__ qg, const float* __restrict__ qb)
{
    __shared__ float kt[64 * 65];
    __shared__ float vt[64 * 65];
    __shared__ float qn_s[Ks][64];
    __shared__ float att_s[Ks][65];
    __shared__ float mr[Ks][2];
    const int tid = threadIdx.x;
    const int b = blockIdx.y, blk = blockIdx.x;
    for (int s = 0; s < Ks; s++) qn_s[s][tid] = g_q[(b * Ks + s) * 64 + tid];
    __syncthreads();
    if (tid < Ks) {
        float sm = 0.f, s2 = 0.f;
        for (int k = 0; k < 64; k++) { float v = qn_s[tid][k]; sm += v; s2 += v * v; }
        float m = sm * (1.f / 64.f);
        mr[tid][0] = m;
        mr[tid][1] = rsqrtf(s2 * (1.f / 64.f) - m * m + 1e-5f);
    }
    __syncthreads();
    for (int s = 0; s < Ks; s++)
        qn_s[s][tid] = (qn_s[s][tid] - mr[s][0]) * mr[s][1] * qg[tid] + qb[tid];
    float pacc[Ks];
#pragma unroll
    for (int s = 0; s < Ks; s++) pacc[s] = 0.f;
    float asum_acc = 0.f;
    const int nbase = blk * (Npix / NBLK);
    for (int t = 0; t < (Npix / NBLK) / 64; t++) {
        int n0 = nbase + t * 64;
        __syncthreads();
        for (int e = tid; e < 4096; e += 64) {
            int n = e >> 6, qq = e & 63;
            kt[n * 65 + qq] = g_keys[((size_t)(b * Npix + n0 + n) << 6) + qq];
            vt[n * 65 + qq] = g_vals[((size_t)(b * Npix + n0 + n) << 6) + qq];
        }
        __syncthreads();
        float lg[Ks];
#pragma unroll
        for (int s = 0; s < Ks; s++) {
            float d = 0.f;
            for (int k = 0; k < 64; k++) d = fmaf(qn_s[s][k], kt[tid * 65 + k], d);
            lg[s] = d * 1.25f;
        }
        float mx = lg[0];
#pragma unroll
        for (int s = 1; s < Ks; s++) mx = fmaxf(mx, lg[s]);
        float den = 0.f, ex[Ks];
#pragma unroll
        for (int s = 0; s < Ks; s++) { ex[s] = expf(lg[s] - mx); den += ex[s]; }
        float inv = 1.f / den;
#pragma unroll
        for (int s = 0; s < Ks; s++) att_s[s][tid] = ex[s] * inv;
        __syncthreads();
        for (int n = 0; n < 64; n++) {
            float v = vt[n * 65 + tid];
#pragma unroll
            for (int s = 0; s < Ks; s++) pacc[s] = fmaf(att_s[s][n], v, pacc[s]);
        }
        if (tid < Ks) {
            float s0 = 0.f;
            for (int n = 0; n < 64; n++) s0 += att_s[tid][n];
            asum_acc += s0;
        }
    }
#pragma unroll
    for (int s = 0; s < Ks; s++)
        g_Ppart[(((size_t)(b * NBLK) + blk) * Ks + s) * 64 + tid] = pacc[s];
    if (tid < Ks) g_attsum[(b * NBLK + blk) * Ks + tid] = asum_acc;
}

__global__ __launch_bounds__(64)
void update_k(const float* __restrict__ wih, const float* __restrict__ whh,
              const float* __restrict__ bih, const float* __restrict__ bhh,
              const float* __restrict__ ug, const float* __restrict__ ub,
              const float* __restrict__ f1w, const float* __restrict__ f1b,
              const float* __restrict__ f2w, const float* __restrict__ f2b)
{
    __shared__ float upd_s[Ks][64];
    __shared__ float q_s[Ks][64];
    __shared__ float gi_s[Ks][192];
    __shared__ float gh_s[Ks][192];
    __shared__ float h_s[Ks][64];
    __shared__ float hn_s[Ks][64];
    __shared__ float a_s[Ks][16];
    __shared__ float stats[Ks][2];
    const int tid = threadIdx.x, b = blockIdx.x;
    float vs = g_valsum[b * 64 + tid];
    for (int s = 0; s < Ks; s++) {
        float p = 0.f, asum = 0.f;
        for (int blk = 0; blk < NBLK; blk++) {
            p    += g_Ppart[(((size_t)(b * NBLK) + blk) * Ks + s) * 64 + tid];
            asum += g_attsum[(b * NBLK + blk) * Ks + s];
        }
        upd_s[s][tid] = p / asum + 1e-8f * vs;
        q_s[s][tid]   = g_q[(b * Ks + s) * 64 + tid];
    }
    __syncthreads();
    for (int e = tid; e < Ks * 192; e += 64) {
        int s = e / 192, j = e - s * 192;
        float si = bih[j], sh = bhh[j];
        const float* wi = &wih[j * 64];
        const float* wh = &whh[j * 64];
        for (int k = 0; k < 64; k++) {
            si = fmaf(upd_s[s][k], wi[k], si);
            sh = fmaf(q_s[s][k],   wh[k], sh);
        }
        gi_s[s][j] = si; gh_s[s][j] = sh;
    }
    __syncthreads();
    for (int s = 0; s < Ks; s++) {
        float r  = 1.f / (1.f + expf(-(gi_s[s][tid] + gh_s[s][tid])));
        float z  = 1.f / (1.f + expf(-(gi_s[s][64 + tid] + gh_s[s][64 + tid])));
        float nn = tanhf(gi_s[s][128 + tid] + r * gh_s[s][128 + tid]);
        h_s[s][tid] = (1.f - z) * nn + z * q_s[s][tid];
    }
    __syncthreads();
    if (tid < Ks) {
        float sm = 0.f, s2 = 0.f;
        for (int k = 0; k < 64; k++) { float v = h_s[tid][k]; sm += v; s2 += v * v; }
        float m = sm * (1.f / 64.f);
        stats[tid][0] = m;
        stats[tid][1] = rsqrtf(s2 * (1.f / 64.f) - m * m + 1e-5f);
    }
    __syncthreads();
    for (int s = 0; s < Ks; s++)
        hn_s[s][tid] = (h_s[s][tid] - stats[s][0]) * stats[s][1] * ug[tid] + ub[tid];
    __syncthreads();
    for (int e = tid; e < Ks * 16; e += 64) {
        int s = e >> 4, i = e & 15;
        float a = f1b[i];
        for (int k = 0; k < 64; k++) a = fmaf(hn_s[s][k], f1w[i * 64 + k], a);
        a_s[s][i] = fmaxf(a, 0.f);
    }
    __syncthreads();
    for (int s = 0; s < Ks; s++) {
        float f = f2b[tid];
#pragma unroll
        for (int i = 0; i < 16; i++) f = fmaf(a_s[s][i], f2w[tid * 16 + i], f);
        g_q[(b * Ks + s) * 64 + tid] = h_s[s][tid] + f;
    }
}

__global__ __launch_bounds__(64)
void final_k(const float* __restrict__ fw, const float* __restrict__ fb,
             float* __restrict__ out)
{
    const int b = blockIdx.x, tid = threadIdx.x;
    if (tid < Ks * 2) {
        int s = tid >> 1, k2 = tid & 1;
        float p = fb[k2];
        for (int k = 0; k < 64; k++)
            p = fmaf(g_q[(b * Ks + s) * 64 + k], fw[k2 * 64 + k], p);
        out[(b * Ks + s) * 2 + k2] = p;
    }
    for (int e = tid; e < Ks * 64; e += 64)
        out[Bn * Ks * 2 + b * Ks * 64 + e] = g_q[b * Ks * 64 + e];
}

extern "C" void kernel_launch(void* const* d_in, const int* in_sizes, int n_in,
                              void* d_out, int out_size)
{
    if (n_in < 28) return;
    static const int exp_sizes[28] = {
        2621440, 14336, 8000, 64, 102400, 64, 102400, 64,
        64, 64, 64, 64, 64, 64, 4096, 64, 4096, 64,
        12288, 12288, 192, 192, 1024, 16, 1024, 64, 128, 2
    };
    for (int i = 0; i < 28; i++)
        if (in_sizes[i] != exp_sizes[i]) {
            fprintf(stderr, "[slotattn] ABORT size[%d]=%d\n", i, in_sizes[i]);
            return;
        }
    const float* data = (const float*)d_in[0];
    const float* slots= (const float*)d_in[1];
    const float* c1w  = (const float*)d_in[2];
    const float* c1b  = (const float*)d_in[3];
    const float* c2w  = (const float*)d_in[4];
    const float* c2b  = (const float*)d_in[5];
    const float* c3w  = (const float*)d_in[6];
    const float* c3b  = (const float*)d_in[7];
    const float* dNg  = (const float*)d_in[8];
    const float* dNb  = (const float*)d_in[9];
    const float* qNg  = (const float*)d_in[10];
    const float* qNb  = (const float*)d_in[11];
    const float* uNg  = (const float*)d_in[12];
    const float* uNb  = (const float*)d_in[13];
    const float* toKw = (const float*)d_in[14];
    const float* toKb = (const float*)d_in[15];
    const float* toVw = (const float*)d_in[16];
    const float* toVb = (const float*)d_in[17];
    const float* gwih = (const float*)d_in[18];
    const float* gwhh = (const float*)d_in[19];
    const float* gbih = (const float*)d_in[20];
    const float* gbhh = (const float*)d_in[21];
    const float* f1w  = (const float*)d_in[22];
    const float* f1b  = (const float*)d_in[23];
    const float* f2w  = (const float*)d_in[24];
    const float* f2b  = (const float*)d_in[25];
    const float* fnw  = (const float*)d_in[26];
    const float* fnb  = (const float*)d_in[27];

    const int PATCHB = 3 * 2 * PBUF * 2;
    const int smem1 = PATCHB + 2 * 4096 + 256;
    const int smem2 = PATCHB + 2 * 16384 + 256;
    cudaFuncSetAttribute(conv_mma<5, 1, true, 0>,  cudaFuncAttributeMaxDynamicSharedMemorySize, smem1);
    cudaFuncSetAttribute(conv_mma<64, 4, true, 1>, cudaFuncAttributeMaxDynamicSharedMemorySize, smem2);
    cudaFuncSetAttribute(conv_mma<64, 4, false, 2>,cudaFuncAttributeMaxDynamicSharedMemorySize, smem2);

    prep_w<<<dim3(25, 3), 256>>>(c1w, c2w, c3w);
    dim3 cg(64, Bn);
    conv_mma<5, 1, true, 0><<<cg, 512, smem1>>>(data, c1b, 0);
    conv_mma<64, 4, true, 1><<<cg, 512, smem2>>>(nullptr, c2b, 102400);
    conv_mma<64, 4, false, 2><<<cg, 512, smem2>>>(nullptr, c3b, 512000);

    kv_ln_gemm<<<dim3(512, Bn), 256>>>(dNg, dNb, toKw, toKb, toVw, toVb);
    valsum_reduce<<<Bn, 64>>>();
    copy_q<<<(Bn * Ks * Qd + 255) / 256, 256>>>(slots, Bn * Ks * Qd);
    for (int it = 0; it < 3; it++) {
        attn_k<<<dim3(NBLK, Bn), 64>>>(qNg, qNb);
        update_k<<<Bn, 64>>>(gwih, gwhh, gbih, gbhh, uNg, uNb, f1w, f1b, f2w, f2b);
    }
    final_k<<<Bn, 64>>>(fnw, fnb, (float*)d_out);
}

// round 17
// speedup vs baseline: 1.8862x; 1.0182x over previous
#include <cuda_runtime.h>
#include <cuda_bf16.h>
#include <math.h>
#include <cstdio>
#include <cstdint>

#define Bn 32
#define HID 64
#define Npix 16384
#define Ks 7
#define Qd 64
#define NBLK 64
#define PROW 72
#define PBUF (136*PROW)

__device__ float g_buf1[(size_t)Bn * HID * Npix];
__device__ float g_buf2[(size_t)Bn * HID * Npix];
__device__ float g_keys[(size_t)Bn * Npix * Qd];
__device__ float g_vals[(size_t)Bn * Npix * Qd];
__device__ float g_valsum[Bn * Qd];
__device__ float g_vsum_part[(size_t)Bn * 512 * 64];
__device__ float g_q[Bn * Ks * Qd];
__device__ float g_Ppart[(size_t)Bn * NBLK * Ks * Qd];
__device__ float g_attsum[Bn * NBLK * Ks];
__device__ __align__(16) unsigned char g_wpack[921600]; // c1@0, c2@102400, c3@512000

__device__ __forceinline__ uint32_t smem_u32(const void* p) {
    uint32_t a;
    asm("{ .reg .u64 t; cvta.to.shared.u64 t, %1; cvt.u32.u64 %0, t; }" : "=r"(a) : "l"(p));
    return a;
}
__device__ __forceinline__ void ldmx2(uint32_t& r0, uint32_t& r1, uint32_t a) {
    asm volatile("ldmatrix.sync.aligned.m8n8.x2.shared.b16 {%0,%1}, [%2];"
                 : "=r"(r0), "=r"(r1) : "r"(a));
}
__device__ __forceinline__ void mma16816(float* d, const uint4& a, uint32_t b0, uint32_t b1) {
    asm volatile("mma.sync.aligned.m16n8k16.row.col.f32.bf16.bf16.f32 "
                 "{%0,%1,%2,%3}, {%4,%5,%6,%7}, {%8,%9}, {%0,%1,%2,%3};"
                 : "+f"(d[0]), "+f"(d[1]), "+f"(d[2]), "+f"(d[3])
                 : "r"(a.x), "r"(a.y), "r"(a.z), "r"(a.w), "r"(b0), "r"(b1));
}

__global__ void prep_w(const float* __restrict__ c1w, const float* __restrict__ c2w,
                       const float* __restrict__ c3w)
{
    const int step = blockIdx.x, conv = blockIdx.y;
    const int ky = step / 5, kx = step - ky * 5;
    const float* w = conv == 0 ? c1w : (conv == 1 ? c2w : c3w);
    const int CIR = conv == 0 ? 5 : 64, CH = conv == 0 ? 1 : 4;
    const size_t base = conv == 0 ? 0 : (conv == 1 ? 102400 : 512000);
    for (int u = threadIdx.x; u < CH * 256; u += 256) {
        int lane = u & 31, s = (u >> 5) & 1, m = (u >> 6) & 3, c = u >> 8;
        int r = lane >> 2, cq = (lane & 3) * 2;
        uint32_t q[4];
        for (int jj = 0; jj < 4; jj++) {
            unsigned short hw[2];
            for (int k2 = 0; k2 < 2; k2++) {
                int j = jj * 2 + k2;
                int co = m * 16 + r + ((j >> 1) & 1) * 8;
                int ci = c * 16 + cq + (j & 1) + (j >> 2) * 8;
                float v = (ci < CIR) ? w[(((size_t)co * CIR + ci) * 5 + ky) * 5 + kx] : 0.f;
                __nv_bfloat16 hv = __float2bfloat16(v);
                __nv_bfloat16 ov = s ? __float2bfloat16(v - __bfloat162float(hv)) : hv;
                hw[k2] = *(unsigned short*)&ov;
            }
            q[jj] = (uint32_t)hw[0] | ((uint32_t)hw[1] << 16);
        }
        *(uint4*)(g_wpack + base + (size_t)(((step * CH + c) * 4 + m) * 2 + s) * 512 + lane * 16)
            = make_uint4(q[0], q[1], q[2], q[3]);
    }
}

// 512 threads: 16 warps = mg(2) x ng(4) x yg(2); 4 ni per warp.
// A operands stream gmem->regs (L2-hot, fragment-packed), pipelined 1 c ahead.
template <int CIR, int CHUNKS, bool RELU, int DIR>
__global__ __launch_bounds__(512, 1)
void conv_mma(const float* __restrict__ ext_in, const float* __restrict__ bias, int wofs)
{
    extern __shared__ char sm[];
    constexpr int ABYTES = CHUNKS * 4096, CISTG = CHUNKS * 16;
    __nv_bfloat16* P = (__nv_bfloat16*)sm;
    float* bias_s = (float*)(sm + 3 * 2 * PBUF * 2);

    const int tid = threadIdx.x, lane = tid & 31, w = tid >> 5;
    const int mg = w & 1, ng = (w >> 1) & 3, yg = w >> 3;
    const int b = blockIdx.y, y0 = blockIdx.x * 2;
    const int il = lane & 7, hf = (lane >> 3) & 1;
    const float* src = (DIR == 0) ? ext_in + (size_t)b * CIR * Npix
                     : ((DIR == 1 ? g_buf1 : g_buf2) + ((size_t)b << 20));
    float* dst = (DIR == 1) ? g_buf2 : g_buf1;
    const uint32_t sbase = smem_u32(sm);

    if (tid < 64) bias_s[tid] = bias[tid];

    auto stage_row = [&](int j) {
        int ry = y0 - 2 + j;
        __nv_bfloat16* ph = P + (j % 3) * 2 * PBUF;
        __nv_bfloat16* pl = ph + PBUF;
        bool rok = (unsigned)ry < 128u;
        for (int e = tid; e < CISTG * 136; e += 512) {
            int ci = e / 136, i = e - ci * 136, x = i - 2;
            float v = 0.f;
            if (rok && (unsigned)x < 128u && ci < CIR)
                v = src[((size_t)ci << 14) + (ry << 7) + x];
            __nv_bfloat16 hv = __float2bfloat16(v);
            ph[i * PROW + ci] = hv;
            pl[i * PROW + ci] = __float2bfloat16(v - __bfloat162float(hv));
        }
    };
    // A fragment gmem address (exact mma fragment layout, 16B per lane)
    auto aptr = [&](int step, int c, int mi, int s) -> const uint4* {
        return (const uint4*)(g_wpack + wofs + (size_t)step * ABYTES
             + (size_t)(((c * 4 + (mg * 2 + mi)) * 2 + s) * 512)) + lane;
    };

    stage_row(0); stage_row(1);

    uint4 cAH[2], cAL[2], nAH[2], nAL[2];
#pragma unroll
    for (int mi = 0; mi < 2; mi++) { cAH[mi] = *aptr(0, 0, mi, 0); cAL[mi] = *aptr(0, 0, mi, 1); }
    __syncthreads();

    float acc[2][4][4];
#pragma unroll
    for (int mi = 0; mi < 2; mi++)
#pragma unroll
        for (int ni = 0; ni < 4; ni++)
#pragma unroll
            for (int k = 0; k < 4; k++) acc[mi][ni][k] = 0.f;

    for (int step = 0; step < 25; step++) {
        const int ky = step / 5, kx = step - ky * 5;
        if (kx == 0 && ky < 4) stage_row(ky + 2);
        const uint32_t pb = sbase + ((ky + yg) % 3) * (2 * PBUF * 2);
#pragma unroll
        for (int c = 0; c < CHUNKS; c++) {
            const bool more = (c + 1 < CHUNKS) || (step + 1 < 25);
            if (more) {
                int ns = (c + 1 < CHUNKS) ? step : step + 1;
                int nc = (c + 1 < CHUNKS) ? c + 1 : 0;
#pragma unroll
                for (int mi = 0; mi < 2; mi++) {
                    nAH[mi] = *aptr(ns, nc, mi, 0);
                    nAL[mi] = *aptr(ns, nc, mi, 1);
                }
            }
#pragma unroll
            for (int ni = 0; ni < 4; ni++) {
                uint32_t bh0, bh1, bl0, bl1;
                uint32_t ra = pb + (uint32_t)(ng * 32 + ni * 8 + kx + il) * 144 + c * 32 + hf * 16;
                ldmx2(bh0, bh1, ra);
                ldmx2(bl0, bl1, ra + PBUF * 2);
                mma16816(acc[0][ni], cAH[0], bh0, bh1);
                mma16816(acc[1][ni], cAH[1], bh0, bh1);
                mma16816(acc[0][ni], cAH[0], bl0, bl1);
                mma16816(acc[1][ni], cAH[1], bl0, bl1);
                mma16816(acc[0][ni], cAL[0], bh0, bh1);
                mma16816(acc[1][ni], cAL[1], bh0, bh1);
            }
            if (more) {
#pragma unroll
                for (int mi = 0; mi < 2; mi++) { cAH[mi] = nAH[mi]; cAL[mi] = nAL[mi]; }
            }
        }
        if (kx == 4) __syncthreads();
    }

    const int r = lane >> 2, cq = (lane & 3) * 2, y = y0 + yg;
#pragma unroll
    for (int mi = 0; mi < 2; mi++) {
        int co = mg * 32 + mi * 16;
        float b0 = bias_s[co + r], b1 = bias_s[co + r + 8];
        float* o0 = dst + ((size_t)(b * 64 + co + r) << 14) + (y << 7);
        float* o1 = dst + ((size_t)(b * 64 + co + r + 8) << 14) + (y << 7);
#pragma unroll
        for (int ni = 0; ni < 4; ni++) {
            int px = ng * 32 + ni * 8 + cq;
            float v0 = acc[mi][ni][0] + b0, v1 = acc[mi][ni][1] + b0;
            float v2 = acc[mi][ni][2] + b1, v3 = acc[mi][ni][3] + b1;
            if (RELU) {
                v0 = fmaxf(v0, 0.f); v1 = fmaxf(v1, 0.f);
                v2 = fmaxf(v2, 0.f); v3 = fmaxf(v3, 0.f);
            }
            *(float2*)(o0 + px) = make_float2(v0, v1);
            *(float2*)(o1 + px) = make_float2(v2, v3);
        }
    }
}

// ---- fused LN + keys/vals GEMM + valsum partials (buf1 -> keys/vals) ----
__global__ __launch_bounds__(256)
void kv_ln_gemm(const float* __restrict__ g, const float* __restrict__ bta,
                const float* __restrict__ wk, const float* __restrict__ bk,
                const float* __restrict__ wv, const float* __restrict__ bv)
{
    __shared__ float a_s[32 * 65];
    __shared__ float w_s[64 * 128];
    __shared__ float mean_s[32], rstd_s[32];
    __shared__ float vs_s[8][64];
    const int tid = threadIdx.x;
    const int b = blockIdx.y, n0 = blockIdx.x * 32;
    const float* enc = g_buf1 + ((size_t)b << 20);

    for (int e = tid; e < 2048; e += 256) {
        int c = e >> 5, j = e & 31;
        a_s[j * 65 + c] = enc[((size_t)c << 14) + n0 + j];
    }
    for (int e = tid; e < 8192; e += 256) {
        int k = e >> 7, o = e & 127;
        w_s[e] = (o < 64) ? wk[o * 64 + k] : wv[(o - 64) * 64 + k];
    }
    __syncthreads();
    if (tid < 32) {
        float s = 0.f, s2 = 0.f;
        for (int c = 0; c < 64; c++) { float v = a_s[tid * 65 + c]; s += v; s2 += v * v; }
        float m = s * (1.f / 64.f);
        mean_s[tid] = m;
        rstd_s[tid] = rsqrtf(s2 * (1.f / 64.f) - m * m + 1e-5f);
    }
    __syncthreads();
    for (int e = tid; e < 2048; e += 256) {
        int j = e >> 6, c = e & 63;
        a_s[j * 65 + c] = (a_s[j * 65 + c] - mean_s[j]) * rstd_s[j] * g[c] + bta[c];
    }
    __syncthreads();

    const int og = tid & 31, ng = tid >> 5;
    float acc[4][4];
#pragma unroll
    for (int i = 0; i < 4; i++)
#pragma unroll
        for (int j = 0; j < 4; j++) acc[i][j] = 0.f;
#pragma unroll 8
    for (int k = 0; k < 64; k++) {
        float av[4];
#pragma unroll
        for (int i = 0; i < 4; i++) av[i] = a_s[(ng * 4 + i) * 65 + k];
        float4 w4 = *(const float4*)&w_s[k * 128 + og * 4];
        float bw[4] = {w4.x, w4.y, w4.z, w4.w};
#pragma unroll
        for (int i = 0; i < 4; i++)
#pragma unroll
            for (int j = 0; j < 4; j++)
                acc[i][j] = fmaf(av[i], bw[j], acc[i][j]);
    }
#pragma unroll
    for (int i = 0; i < 4; i++) {
        int n = n0 + ng * 4 + i;
#pragma unroll
        for (int j = 0; j < 4; j++) {
            int o = og * 4 + j;
            if (o < 64) g_keys[((size_t)(b * Npix + n) << 6) + o] = acc[i][j] + bk[o];
            else        g_vals[((size_t)(b * Npix + n) << 6) + (o - 64)] = acc[i][j] + bv[o - 64];
        }
    }
    if (og >= 16) {
#pragma unroll
        for (int j = 0; j < 4; j++) {
            int o = og * 4 + j - 64;
            vs_s[ng][o] = acc[0][j] + acc[1][j] + acc[2][j] + acc[3][j] + 4.f * bv[o];
        }
    }
    __syncthreads();
    if (tid < 64) {
        float s = 0.f;
        for (int p = 0; p < 8; p++) s += vs_s[p][tid];
        g_vsum_part[((size_t)b * 512 + blockIdx.x) * 64 + tid] = s;
    }
}

__global__ __launch_bounds__(64)
void valsum_reduce()
{
    const int b = blockIdx.x, q = threadIdx.x;
    float s = 0.f;
    for (int p = 0; p < 512; p++) s += g_vsum_part[((size_t)b * 512 + p) * 64 + q];
    g_valsum[b * 64 + q] = s;
}

__global__ void copy_q(const float* __restrict__ src, int n)
{
    int i = blockIdx.x * 256 + threadIdx.x;
    if (i < n) g_q[i] = src[i];
}

__global__ __launch_bounds__(64)
void attn_k(const float* __restrict__ qg, const float* __restrict__ qb)
{
    __shared__ float kt[64 * 65];
    __shared__ float vt[64 * 65];
    __shared__ float qn_s[Ks][64];
    __shared__ float att_s[Ks][65];
    __shared__ float mr[Ks][2];
    const int tid = threadIdx.x;
    const int b = blockIdx.y, blk = blockIdx.x;
    for (int s = 0; s < Ks; s++) qn_s[s][tid] = g_q[(b * Ks + s) * 64 + tid];
    __syncthreads();
    if (tid < Ks) {
        float sm = 0.f, s2 = 0.f;
        for (int k = 0; k < 64; k++) { float v = qn_s[tid][k]; sm += v; s2 += v * v; }
        float m = sm * (1.f / 64.f);
        mr[tid][0] = m;
        mr[tid][1] = rsqrtf(s2 * (1.f / 64.f) - m * m + 1e-5f);
    }
    __syncthreads();
    for (int s = 0; s < Ks; s++)
        qn_s[s][tid] = (qn_s[s][tid] - mr[s][0]) * mr[s][1] * qg[tid] + qb[tid];
    float pacc[Ks];
#pragma unroll
    for (int s = 0; s < Ks; s++) pacc[s] = 0.f;
    float asum_acc = 0.f;
    const int nbase = blk * (Npix / NBLK);
    for (int t = 0; t < (Npix / NBLK) / 64; t++) {
        int n0 = nbase + t * 64;
        __syncthreads();
        for (int e = tid; e < 4096; e += 64) {
            int n = e >> 6, qq = e & 63;
            kt[n * 65 + qq] = g_keys[((size_t)(b * Npix + n0 + n) << 6) + qq];
            vt[n * 65 + qq] = g_vals[((size_t)(b * Npix + n0 + n) << 6) + qq];
        }
        __syncthreads();
        float lg[Ks];
#pragma unroll
        for (int s = 0; s < Ks; s++) {
            float d = 0.f;
            for (int k = 0; k < 64; k++) d = fmaf(qn_s[s][k], kt[tid * 65 + k], d);
            lg[s] = d * 1.25f;
        }
        float mx = lg[0];
#pragma unroll
        for (int s = 1; s < Ks; s++) mx = fmaxf(mx, lg[s]);
        float den = 0.f, ex[Ks];
#pragma unroll
        for (int s = 0; s < Ks; s++) { ex[s] = expf(lg[s] - mx); den += ex[s]; }
        float inv = 1.f / den;
#pragma unroll
        for (int s = 0; s < Ks; s++) att_s[s][tid] = ex[s] * inv;
        __syncthreads();
        for (int n = 0; n < 64; n++) {
            float v = vt[n * 65 + tid];
#pragma unroll
            for (int s = 0; s < Ks; s++) pacc[s] = fmaf(att_s[s][n], v, pacc[s]);
        }
        if (tid < Ks) {
            float s0 = 0.f;
            for (int n = 0; n < 64; n++) s0 += att_s[tid][n];
            asum_acc += s0;
        }
    }
#pragma unroll
    for (int s = 0; s < Ks; s++)
        g_Ppart[(((size_t)(b * NBLK) + blk) * Ks + s) * 64 + tid] = pacc[s];
    if (tid < Ks) g_attsum[(b * NBLK + blk) * Ks + tid] = asum_acc;
}

__global__ __launch_bounds__(64)
void update_k(const float* __restrict__ wih, const float* __restrict__ whh,
              const float* __restrict__ bih, const float* __restrict__ bhh,
              const float* __restrict__ ug, const float* __restrict__ ub,
              const float* __restrict__ f1w, const float* __restrict__ f1b,
              const float* __restrict__ f2w, const float* __restrict__ f2b)
{
    __shared__ float upd_s[Ks][64];
    __shared__ float q_s[Ks][64];
    __shared__ float gi_s[Ks][192];
    __shared__ float gh_s[Ks][192];
    __shared__ float h_s[Ks][64];
    __shared__ float hn_s[Ks][64];
    __shared__ float a_s[Ks][16];
    __shared__ float stats[Ks][2];
    const int tid = threadIdx.x, b = blockIdx.x;
    float vs = g_valsum[b * 64 + tid];
    for (int s = 0; s < Ks; s++) {
        float p = 0.f, asum = 0.f;
        for (int blk = 0; blk < NBLK; blk++) {
            p    += g_Ppart[(((size_t)(b * NBLK) + blk) * Ks + s) * 64 + tid];
            asum += g_attsum[(b * NBLK + blk) * Ks + s];
        }
        upd_s[s][tid] = p / asum + 1e-8f * vs;
        q_s[s][tid]   = g_q[(b * Ks + s) * 64 + tid];
    }
    __syncthreads();
    for (int e = tid; e < Ks * 192; e += 64) {
        int s = e / 192, j = e - s * 192;
        float si = bih[j], sh = bhh[j];
        const float* wi = &wih[j * 64];
        const float* wh = &whh[j * 64];
        for (int k = 0; k < 64; k++) {
            si = fmaf(upd_s[s][k], wi[k], si);
            sh = fmaf(q_s[s][k],   wh[k], sh);
        }
        gi_s[s][j] = si; gh_s[s][j] = sh;
    }
    __syncthreads();
    for (int s = 0; s < Ks; s++) {
        float r  = 1.f / (1.f + expf(-(gi_s[s][tid] + gh_s[s][tid])));
        float z  = 1.f / (1.f + expf(-(gi_s[s][64 + tid] + gh_s[s][64 + tid])));
        float nn = tanhf(gi_s[s][128 + tid] + r * gh_s[s][128 + tid]);
        h_s[s][tid] = (1.f - z) * nn + z * q_s[s][tid];
    }
    __syncthreads();
    if (tid < Ks) {
        float sm = 0.f, s2 = 0.f;
        for (int k = 0; k < 64; k++) { float v = h_s[tid][k]; sm += v; s2 += v * v; }
        float m = sm * (1.f / 64.f);
        stats[tid][0] = m;
        stats[tid][1] = rsqrtf(s2 * (1.f / 64.f) - m * m + 1e-5f);
    }
    __syncthreads();
    for (int s = 0; s < Ks; s++)
        hn_s[s][tid] = (h_s[s][tid] - stats[s][0]) * stats[s][1] * ug[tid] + ub[tid];
    __syncthreads();
    for (int e = tid; e < Ks * 16; e += 64) {
        int s = e >> 4, i = e & 15;
        float a = f1b[i];
        for (int k = 0; k < 64; k++) a = fmaf(hn_s[s][k], f1w[i * 64 + k], a);
        a_s[s][i] = fmaxf(a, 0.f);
    }
    __syncthreads();
    for (int s = 0; s < Ks; s++) {
        float f = f2b[tid];
#pragma unroll
        for (int i = 0; i < 16; i++) f = fmaf(a_s[s][i], f2w[tid * 16 + i], f);
        g_q[(b * Ks + s) * 64 + tid] = h_s[s][tid] + f;
    }
}

__global__ __launch_bounds__(64)
void final_k(const float* __restrict__ fw, const float* __restrict__ fb,
             float* __restrict__ out)
{
    const int b = blockIdx.x, tid = threadIdx.x;
    if (tid < Ks * 2) {
        int s = tid >> 1, k2 = tid & 1;
        float p = fb[k2];
        for (int k = 0; k < 64; k++)
            p = fmaf(g_q[(b * Ks + s) * 64 + k], fw[k2 * 64 + k], p);
        out[(b * Ks + s) * 2 + k2] = p;
    }
    for (int e = tid; e < Ks * 64; e += 64)
        out[Bn * Ks * 2 + b * Ks * 64 + e] = g_q[b * Ks * 64 + e];
}

extern "C" void kernel_launch(void* const* d_in, const int* in_sizes, int n_in,
                              void* d_out, int out_size)
{
    if (n_in < 28) return;
    static const int exp_sizes[28] = {
        2621440, 14336, 8000, 64, 102400, 64, 102400, 64,
        64, 64, 64, 64, 64, 64, 4096, 64, 4096, 64,
        12288, 12288, 192, 192, 1024, 16, 1024, 64, 128, 2
    };
    for (int i = 0; i < 28; i++)
        if (in_sizes[i] != exp_sizes[i]) {
            fprintf(stderr, "[slotattn] ABORT size[%d]=%d\n", i, in_sizes[i]);
            return;
        }
    const float* data = (const float*)d_in[0];
    const float* slots= (const float*)d_in[1];
    const float* c1w  = (const float*)d_in[2];
    const float* c1b  = (const float*)d_in[3];
    const float* c2w  = (const float*)d_in[4];
    const float* c2b  = (const float*)d_in[5];
    const float* c3w  = (const float*)d_in[6];
    const float* c3b  = (const float*)d_in[7];
    const float* dNg  = (const float*)d_in[8];
    const float* dNb  = (const float*)d_in[9];
    const float* qNg  = (const float*)d_in[10];
    const float* qNb  = (const float*)d_in[11];
    const float* uNg  = (const float*)d_in[12];
    const float* uNb  = (const float*)d_in[13];
    const float* toKw = (const float*)d_in[14];
    const float* toKb = (const float*)d_in[15];
    const float* toVw = (const float*)d_in[16];
    const float* toVb = (const float*)d_in[17];
    const float* gwih = (const float*)d_in[18];
    const float* gwhh = (const float*)d_in[19];
    const float* gbih = (const float*)d_in[20];
    const float* gbhh = (const float*)d_in[21];
    const float* f1w  = (const float*)d_in[22];
    const float* f1b  = (const float*)d_in[23];
    const float* f2w  = (const float*)d_in[24];
    const float* f2b  = (const float*)d_in[25];
    const float* fnw  = (const float*)d_in[26];
    const float* fnb  = (const float*)d_in[27];

    const int smemc = 3 * 2 * PBUF * 2 + 256;   // patch ring + bias
    cudaFuncSetAttribute(conv_mma<5, 1, true, 0>,  cudaFuncAttributeMaxDynamicSharedMemorySize, smemc);
    cudaFuncSetAttribute(conv_mma<64, 4, true, 1>, cudaFuncAttributeMaxDynamicSharedMemorySize, smemc);
    cudaFuncSetAttribute(conv_mma<64, 4, false, 2>,cudaFuncAttributeMaxDynamicSharedMemorySize, smemc);

    prep_w<<<dim3(25, 3), 256>>>(c1w, c2w, c3w);
    dim3 cg(64, Bn);
    conv_mma<5, 1, true, 0><<<cg, 512, smemc>>>(data, c1b, 0);
    conv_mma<64, 4, true, 1><<<cg, 512, smemc>>>(nullptr, c2b, 102400);
    conv_mma<64, 4, false, 2><<<cg, 512, smemc>>>(nullptr, c3b, 512000);

    kv_ln_gemm<<<dim3(512, Bn), 256>>>(dNg, dNb, toKw, toKb, toVw, toVb);
    valsum_reduce<<<Bn, 64>>>();
    copy_q<<<(Bn * Ks * Qd + 255) / 256, 256>>>(slots, Bn * Ks * Qd);
    for (int it = 0; it < 3; it++) {
        attn_k<<<dim3(NBLK, Bn), 64>>>(qNg, qNb);
        update_k<<<Bn, 64>>>(gwih, gwhh, gbih, gbhh, uNg, uNb, f1w, f1b, f2w, f2b);
    }
    final_k<<<Bn, 64>>>(fnw, fnb, (float*)d_out);
}